// round 4
// baseline (speedup 1.0000x reference)
#include <cuda_runtime.h>
#include <cstdint>

// Conv2d: x[3,2048,2048] (fp32) * k[16,3,3,3] (fp32), pad=1, stride=1 -> out[16,2048,2048]
//
// Strategy: direct conv, fp32 packed-pair math via sm_103a `fma.rn.f32x2` (FFMA2).
//   - block = 256 threads, output tile 8 rows x 128 cols, all 16 OC.
//   - input tile (3 x 10 x 130 + halo) in smem, zero-padded at image edges.
//   - weights in smem, pre-broadcast-packed as (w,w) u64 pairs -> 1 LDS.64 per tap*oc.
//   - each thread: 4 consecutive pixels x 16 OC = 64 fp32 accs held as 32 f32x2 pairs.
//     Per thread: 27 taps * 16 oc * 2 pairs = 864 FFMA2, 432 broadcast LDS.64.

#define HW   2048
#define PLANE (2048 * 2048)

__device__ __forceinline__ unsigned long long pack2(float a, float b) {
    unsigned long long r;
    asm("mov.b64 %0, {%1, %2};"
        : "=l"(r) : "r"(__float_as_uint(a)), "r"(__float_as_uint(b)));
    return r;
}

__device__ __forceinline__ void ffma2(unsigned long long& d,
                                      unsigned long long a,
                                      unsigned long long b) {
    asm("fma.rn.f32x2 %0, %1, %2, %0;" : "+l"(d) : "l"(a), "l"(b));
}

__device__ __forceinline__ float2 unpack2(unsigned long long v) {
    unsigned lo, hi;
    asm("mov.b64 {%0, %1}, %2;" : "=r"(lo), "=r"(hi) : "l"(v));
    return make_float2(__uint_as_float(lo), __uint_as_float(hi));
}

__global__ __launch_bounds__(256, 2)
void conv3x3_f32x2_kernel(const float* __restrict__ x,
                          const float* __restrict__ kern,
                          float* __restrict__ out) {
    // Input tile: 3 channels, 8 rows + 2 halo, 128 cols + 2 halo (padded to 132 for
    // 16B-aligned rows: 132*4 = 528 = 16*33).
    __shared__ __align__(16) float s_in[3][10][132];
    // Weights as (w,w) packed u64, layout [ic][kh][kw][oc].
    __shared__ unsigned long long s_w[432];

    const int tid = threadIdx.x;
    const int bx = blockIdx.x;   // 16 tiles of 128 cols
    const int by = blockIdx.y;   // 256 tiles of 8 rows
    const int row0 = by * 8 - 1;
    const int col0 = bx * 128 - 1;

    // ---- Stage weights: transpose [oc][ic][kh][kw] -> [tap][oc], broadcast-pack ----
    for (int i = tid; i < 432; i += 256) {
        unsigned u = __float_as_uint(kern[i]);
        int oc = i / 27;
        int t  = i - oc * 27;           // ic*9 + kh*3 + kw
        s_w[t * 16 + oc] = ((unsigned long long)u << 32) | u;
    }

    // ---- Stage input tile with zero padding (3 * 10 * 130 = 3900 elems) ----
    for (int i = tid; i < 3900; i += 256) {
        int ic  = i / 1300;
        int rem = i - ic * 1300;
        int r   = rem / 130;
        int c   = rem - r * 130;
        int gy = row0 + r;
        int gx = col0 + c;
        float v = 0.0f;
        if ((unsigned)gy < (unsigned)HW && (unsigned)gx < (unsigned)HW)
            v = x[ic * PLANE + gy * HW + gx];
        s_in[ic][r][c] = v;
    }
    __syncthreads();

    const int tx = tid & 31;    // 32 threads across W, 4 pixels each
    const int ty = tid >> 5;    // 8 rows

    // acc[2*oc+0] = pixels (0,1), acc[2*oc+1] = pixels (2,3) for output channel oc
    unsigned long long acc[32];
    #pragma unroll
    for (int i = 0; i < 32; ++i) acc[i] = 0ull;

    #pragma unroll
    for (int ic = 0; ic < 3; ++ic) {
        #pragma unroll
        for (int kh = 0; kh < 3; ++kh) {
            const float* rp = &s_in[ic][ty + kh][tx * 4];
            float4 v4 = *reinterpret_cast<const float4*>(rp);      // i0..i3 (16B aligned)
            float2 v2 = *reinterpret_cast<const float2*>(rp + 4);  // i4,i5
            // Shifted input pairs for kw = 0,1,2:
            unsigned long long p01 = pack2(v4.x, v4.y);
            unsigned long long p23 = pack2(v4.z, v4.w);
            unsigned long long p12 = pack2(v4.y, v4.z);
            unsigned long long p34 = pack2(v4.w, v2.x);
            unsigned long long p45 = pack2(v2.x, v2.y);
            const unsigned long long* wp = &s_w[(ic * 9 + kh * 3) * 16];

            #pragma unroll
            for (int oc = 0; oc < 16; ++oc) {          // kw = 0
                unsigned long long w0 = wp[oc];
                ffma2(acc[2 * oc],     p01, w0);
                ffma2(acc[2 * oc + 1], p23, w0);
            }
            #pragma unroll
            for (int oc = 0; oc < 16; ++oc) {          // kw = 1
                unsigned long long w1 = wp[16 + oc];
                ffma2(acc[2 * oc],     p12, w1);
                ffma2(acc[2 * oc + 1], p34, w1);
            }
            #pragma unroll
            for (int oc = 0; oc < 16; ++oc) {          // kw = 2
                unsigned long long w2 = wp[32 + oc];
                ffma2(acc[2 * oc],     p23, w2);
                ffma2(acc[2 * oc + 1], p45, w2);
            }
        }
    }

    // ---- Epilogue: 16 x float4 coalesced stores ----
    const int orow = by * 8 + ty;
    const int ocol = bx * 128 + tx * 4;
    float* ob = out + orow * HW + ocol;
    #pragma unroll
    for (int oc = 0; oc < 16; ++oc) {
        float2 lo = unpack2(acc[2 * oc]);
        float2 hi = unpack2(acc[2 * oc + 1]);
        float4 o = make_float4(lo.x, lo.y, hi.x, hi.y);
        *reinterpret_cast<float4*>(ob + oc * PLANE) = o;
    }
}

extern "C" void kernel_launch(void* const* d_in, const int* in_sizes, int n_in,
                              void* d_out, int out_size) {
    const float* x = (const float*)d_in[0];   // [3, 2048, 2048]
    const float* k = (const float*)d_in[1];   // [16, 3, 3, 3]
    float* out     = (float*)d_out;           // [16, 2048, 2048]

    dim3 grid(HW / 128, HW / 8);   // (16, 256)
    conv3x3_f32x2_kernel<<<grid, 256>>>(x, k, out);
}